// round 2
// baseline (speedup 1.0000x reference)
#include <cuda_runtime.h>

#define NLNK 64
#define NB   16
#define NP   20
#define T    512
#define PAD  128
#define NT   128
#define DTC  0.01f
#define NOISEC 0.001f
#define LN2C 0.69314718055994530942f

__device__ float g_partial[NB * NLNK];

__global__ void __launch_bounds__(NT) outage_kernel(const float* __restrict__ pathloss,
                                                    const float* __restrict__ powers) {
    __shared__ __align__(16) float Qbuf[2][PAD + T];
    __shared__ __align__(16) float krev[T];
    __shared__ float p2[T], p2m1[T];
    __shared__ float s_arr[NP];
    __shared__ float out20[NP];
    __shared__ float red[64];
    __shared__ float sc_diag, sc_rs;

    const int c    = blockIdx.x;
    const int b    = c >> 6;
    const int l    = c & 63;
    const int tid  = threadIdx.x;
    const int warp = tid >> 5;
    const int lane = tid & 31;

    // row sum + diagonal of pathloss row l
    if (tid < 64) red[tid] = pathloss[l * 64 + tid];

    // 2^t and 2^t - 1 tables (t_arr = t*0.01)
    for (int t = tid; t < T; t += NT) {
        float v = exp2f((float)t * DTC);
        p2[t]   = v;
        p2m1[t] = v - 1.0f;
    }
    // zero the left padding of both ping-pong buffers (kills all triangular branches)
    for (int i = tid; i < PAD; i += NT) { Qbuf[0][i] = 0.0f; Qbuf[1][i] = 0.0f; }
    __syncthreads();

    if (tid == 0) {
        float rs = 0.0f;
        for (int j = 0; j < 64; j++) rs += red[j];
        sc_rs   = rs;
        sc_diag = pathloss[l * 64 + l];
    }
    __syncthreads();

    if (tid < NP) {
        float p    = powers[(b * NP + tid) * NLNK + l];
        float diag = sc_diag;
        s_arr[tid] = diag * p / (p * (sc_rs - diag) + NOISEC);
    }
    __syncthreads();

    // Q^(0)[t] = 1 - exp(-(2^t-1)*s0)
    {
        float s0 = s_arr[0];
        for (int t = tid; t < T; t += NT)
            Qbuf[0][PAD + t] = 1.0f - __expf(-p2m1[t] * s0);
    }
    __syncthreads();
    if (tid == 0) out20[0] = Qbuf[0][PAD + T - 1];

    // Warp -> t-range assignment, rotated per block so heavy ranges spread over SMSPs
    const int trange = (warp + blockIdx.x) & 3;
    const int t0     = 4 * (trange * 32 + lane);   // 4 contiguous outputs per thread
    const int G      = 32 * (trange + 1);          // m-groups needed (triangular bound)

    int cur = 0;
    for (int n = 1; n < NP; n++) {
        // build reversed kernel: krev[m] = exp(-(2^u-1)s) * 2^u * s * ln2, u = T-1-m
        float s  = s_arr[n];
        float sl = s * LN2C;
        for (int m = tid; m < T; m += NT) {
            int u = T - 1 - m;
            krev[m] = __expf(-p2m1[u] * s) * p2[u] * sl;
        }
        __syncthreads();

        const float4* Kq = (const float4*)krev;
        const float*  Qc = &Qbuf[cur][PAD];
        float acc0 = 0.f, acc1 = 0.f, acc2 = 0.f, acc3 = 0.f;
        float4 a = *(const float4*)(Qc + t0);              // Q[t0 .. t0+3]
        const float4* qp = (const float4*)(Qc + t0 - 4);   // next-lower quad
        #pragma unroll 4
        for (int g = 0; g < G; g++) {
            float4 bq = *qp; qp--;                         // Q[t0-4g-4 .. t0-4g-1]
            float4 kq = Kq[g];
            // m = 4g..4g+3, outputs r=0..3 read sliding window (a = Q[t0-4g .. t0+3-4g])
            acc0 += a.x  * kq.x; acc1 += a.y  * kq.x; acc2 += a.z  * kq.x; acc3 += a.w * kq.x;
            acc0 += bq.w * kq.y; acc1 += a.x  * kq.y; acc2 += a.y  * kq.y; acc3 += a.z * kq.y;
            acc0 += bq.z * kq.z; acc1 += bq.w * kq.z; acc2 += a.x  * kq.z; acc3 += a.y * kq.z;
            acc0 += bq.y * kq.w; acc1 += bq.z * kq.w; acc2 += bq.w * kq.w; acc3 += a.x * kq.w;
            a = bq;
        }
        float4 outq = make_float4(acc0 * DTC, acc1 * DTC, acc2 * DTC, acc3 * DTC);
        *(float4*)(&Qbuf[cur ^ 1][PAD + t0]) = outq;
        if (t0 == T - 4) out20[n] = outq.w;                // Q^(n)[511]
        __syncthreads();
        cur ^= 1;
    }

    if (tid == 0) {
        // contrib = p0 + 1 + sum_{n=0..18} (p[n+1]+1)*o[n] + o[19]
        float contrib = powers[(b * NP) * NLNK + l] + 1.0f;
        #pragma unroll
        for (int n = 0; n < NP - 1; n++)
            contrib += (powers[(b * NP + n + 1) * NLNK + l] + 1.0f) * out20[n];
        contrib += out20[NP - 1];
        g_partial[c] = contrib;
    }
}

__global__ void reduce_kernel(float* __restrict__ out) {
    __shared__ float sh[256];
    int tid = threadIdx.x;
    sh[tid] = g_partial[tid] + g_partial[tid + 256] + g_partial[tid + 512] + g_partial[tid + 768];
    __syncthreads();
    for (int s = 128; s > 0; s >>= 1) {
        if (tid < s) sh[tid] += sh[tid + s];
        __syncthreads();
    }
    if (tid == 0) out[0] = sh[0];
}

extern "C" void kernel_launch(void* const* d_in, const int* in_sizes, int n_in,
                              void* d_out, int out_size) {
    const float* a0 = (const float*)d_in[0];
    const float* a1 = (const float*)d_in[1];
    const float* pathloss = a0;
    const float* powers   = a1;
    if (n_in >= 2 && in_sizes[0] != NLNK * NLNK) { pathloss = a1; powers = a0; }
    outage_kernel<<<NB * NLNK, NT>>>(pathloss, powers);
    reduce_kernel<<<1, 256>>>((float*)d_out);
}